// round 4
// baseline (speedup 1.0000x reference)
#include <cuda_runtime.h>
#include <cstdint>
#include <math.h>
#include <mma.h>

using namespace nvcuda;

#define DIM 128

// ---------------- scratch (device globals; no allocation allowed) ----------------
__device__ int g_deg   [600000];   // 8 segments: src/dst degrees per etype
__device__ float g_norm[600000];
__device__ int g_base  [300000];   // CSR row starts: [dd_dst | gd_dst | dg_dst | gg_dst]
__device__ int g_cursor[300000];
__device__ int g_bsum  [512];
__device__ int g_ebuf  [2400000];  // binned src indices

// ---------------- zero deg ----------------
__global__ void zero_deg() {
    int i = blockIdx.x * blockDim.x + threadIdx.x;
    if (i < 600000 / 4) ((int4*)g_deg)[i] = make_int4(0, 0, 0, 0);
}

// ---------------- degree counting (all 4 etypes) ----------------
__global__ void deg_all(const int* __restrict__ s0, const int* __restrict__ d0, int o0s, int o0d,
                        const int* __restrict__ s1, const int* __restrict__ d1, int o1s, int o1d,
                        const int* __restrict__ s2, const int* __restrict__ d2, int o2s, int o2d,
                        const int* __restrict__ s3, const int* __restrict__ d3, int o3s, int o3d,
                        int E) {
    int i = blockIdx.x * blockDim.x + threadIdx.x;
    const int *s, *d; int os, od, j;
    if (i < E)          { s = s0; d = d0; os = o0s; od = o0d; j = i; }
    else if (i < 2 * E) { s = s1; d = d1; os = o1s; od = o1d; j = i - E; }
    else if (i < 3 * E) { s = s2; d = d2; os = o2s; od = o2d; j = i - 2 * E; }
    else if (i < 4 * E) { s = s3; d = d3; os = o3s; od = o3d; j = i - 3 * E; }
    else return;
    atomicAdd(&g_deg[os + __ldg(s + j)], 1);
    atomicAdd(&g_deg[od + __ldg(d + j)], 1);
}

__global__ void norm_kernel(int n) {
    int i = blockIdx.x * blockDim.x + threadIdx.x;
    if (i < n) g_norm[i] = rsqrtf(fmaxf((float)g_deg[i], 1.0f));
}

// ---------------- 3-phase exclusive scan over concatenated dst degrees ----------------
#define SCAN_BLK 1024
__global__ void scan1(int total, int nDrug, int nGene,
                      int o_dd_d, int o_gd_d, int o_dg_d, int o_gg_d) {
    __shared__ int sh[256];
    const int tid = threadIdx.x;
    const int base = blockIdx.x * SCAN_BLK + tid * 4;
    const int c1 = nDrug, c2 = 2 * nDrug, c3 = 2 * nDrug + nGene;
    int v[4], ssum = 0;
    #pragma unroll
    for (int q = 0; q < 4; q++) {
        int i = base + q, d = 0;
        if (i < total) {
            int idx;
            if (i < c1)      idx = o_dd_d + i;
            else if (i < c2) idx = o_gd_d + i - c1;
            else if (i < c3) idx = o_dg_d + i - c2;
            else             idx = o_gg_d + i - c3;
            d = g_deg[idx];
        }
        v[q] = d; ssum += d;
    }
    sh[tid] = ssum; __syncthreads();
    for (int off = 1; off < 256; off <<= 1) {
        int t = (tid >= off) ? sh[tid - off] : 0;
        __syncthreads();
        sh[tid] += t;
        __syncthreads();
    }
    int run = sh[tid] - ssum;
    if (tid == 255) g_bsum[blockIdx.x] = sh[255];
    #pragma unroll
    for (int q = 0; q < 4; q++) {
        int i = base + q;
        if (i < total) g_base[i] = run;
        run += v[q];
    }
}

__global__ void scan2(int n) {
    __shared__ int sh[512];
    int tid = threadIdx.x;
    int v = (tid < n) ? g_bsum[tid] : 0;
    sh[tid] = v; __syncthreads();
    for (int off = 1; off < 512; off <<= 1) {
        int t = (tid >= off) ? sh[tid - off] : 0;
        __syncthreads();
        sh[tid] += t;
        __syncthreads();
    }
    if (tid < n) g_bsum[tid] = sh[tid] - v;
}

__global__ void scan3(int total) {
    int i = blockIdx.x * blockDim.x + threadIdx.x;
    if (i < total) {
        int v = g_base[i] + g_bsum[i / SCAN_BLK];
        g_base[i] = v;
        g_cursor[i] = v;
    }
}

// ---------------- binning: ebuf[pos] = src (CSR by dst), all 4 etypes ----------------
// segment order MUST match scan: dd, gd, dg, gg
__global__ void bin_all(const int* __restrict__ s0, const int* __restrict__ d0,
                        const int* __restrict__ s1, const int* __restrict__ d1,
                        const int* __restrict__ s2, const int* __restrict__ d2,
                        const int* __restrict__ s3, const int* __restrict__ d3,
                        int E, int nDrug, int nGene) {
    int i = blockIdx.x * blockDim.x + threadIdx.x;
    const int *s, *d; int off, j;
    if (i < E)          { s = s0; d = d0; off = 0;                 j = i; }
    else if (i < 2 * E) { s = s1; d = d1; off = nDrug;             j = i - E; }
    else if (i < 3 * E) { s = s2; d = d2; off = 2 * nDrug;         j = i - 2 * E; }
    else if (i < 4 * E) { s = s3; d = d3; off = 2 * nDrug + nGene; j = i - 3 * E; }
    else return;
    int dd = __ldg(d + j);
    int pos = atomicAdd(&g_cursor[off + dd], 1);
    g_ebuf[pos] = __ldg(s + j);
}

// ---------------- fused gather + WMMA tf32 GEMM + bias/relu/L2norm ----------------
// Per CTA: 128 dst rows. For K-chunk kc (etype kc): warp gathers its 16 rows'
// edge lists (acc += norm_src[s]*x[s,:]), scales by norm_dst, tf32-rounds into As,
// then m16n16k8 WMMA over K=128; accumulate across both chunks; fused epilogue.
#define APAD 132
#define BPAD 132
#define GEMM_SMEM ((256 * BPAD + 128 * APAD + 128) * 4)   // 203264 B

__global__ void __launch_bounds__(256, 1)
gemm_gather(const float* __restrict__ x0, const float* __restrict__ x1,
            const int* __restrict__ base0, const int* __restrict__ base1,
            const int* __restrict__ deg0, const int* __restrict__ deg1,
            const float* __restrict__ nsrc0, const float* __restrict__ nsrc1,
            const float* __restrict__ nd0, const float* __restrict__ nd1,
            const float* __restrict__ W0, const float* __restrict__ W1,
            const float* __restrict__ bias,
            float* __restrict__ out, int M) {
    extern __shared__ float sm[];
    float* Bs = sm;                            // [256][BPAD]
    float* As = sm + 256 * BPAD;               // [128][APAD] (A chunk, later C scratch)
    float* bs = sm + 256 * BPAD + 128 * APAD;  // [128]
    const int tid = threadIdx.x, wid = tid >> 5, lane = tid & 31;

    if (tid < 128) bs[tid] = __ldg(bias + tid);

    // Stage Wcat[k][n] (k<128: W0, else W1), tf32-rounded.
    for (int i = tid; i < 256 * 128; i += 256) {
        int k = i >> 7, n = i & 127;
        float v = (k < 128) ? __ldg(W0 + k * 128 + n) : __ldg(W1 + (k - 128) * 128 + n);
        Bs[k * BPAD + n] = wmma::__float_to_tf32(v);
    }

    const int rowBase = blockIdx.x * 128;
    const int wrow = wid * 16;

    wmma::fragment<wmma::accumulator, 16, 16, 8, float> c[8];
    #pragma unroll
    for (int t = 0; t < 8; t++) wmma::fill_fragment(c[t], 0.0f);

    for (int kc = 0; kc < 2; kc++) {
        __syncthreads();   // prev chunk's MMA done (and Bs staged on first pass)
        const float4* xv = (const float4*)(kc ? x1 : x0);
        const int* bp    = kc ? base1 : base0;
        const int* dp    = kc ? deg1  : deg0;
        const float* ns  = kc ? nsrc1 : nsrc0;
        const float* nd  = kc ? nd1   : nd0;

        // Gather: each warp builds rows wrow..wrow+15 of this chunk.
        for (int rr = 0; rr < 16; rr++) {
            const int row = wrow + rr, gr = rowBase + row;
            float4 acc = make_float4(0.f, 0.f, 0.f, 0.f);
            if (gr < M) {
                int j = __ldg(bp + gr);
                const int e = j + __ldg(dp + gr);
                for (; j + 4 <= e; j += 4) {
                    int s0 = __ldg(g_ebuf + j),     s1 = __ldg(g_ebuf + j + 1);
                    int s2 = __ldg(g_ebuf + j + 2), s3 = __ldg(g_ebuf + j + 3);
                    float w0 = __ldg(ns + s0), w1 = __ldg(ns + s1);
                    float w2 = __ldg(ns + s2), w3 = __ldg(ns + s3);
                    float4 v0 = __ldg(xv + s0 * 32 + lane);
                    float4 v1 = __ldg(xv + s1 * 32 + lane);
                    float4 v2 = __ldg(xv + s2 * 32 + lane);
                    float4 v3 = __ldg(xv + s3 * 32 + lane);
                    acc.x = fmaf(w0, v0.x, fmaf(w1, v1.x, fmaf(w2, v2.x, fmaf(w3, v3.x, acc.x))));
                    acc.y = fmaf(w0, v0.y, fmaf(w1, v1.y, fmaf(w2, v2.y, fmaf(w3, v3.y, acc.y))));
                    acc.z = fmaf(w0, v0.z, fmaf(w1, v1.z, fmaf(w2, v2.z, fmaf(w3, v3.z, acc.z))));
                    acc.w = fmaf(w0, v0.w, fmaf(w1, v1.w, fmaf(w2, v2.w, fmaf(w3, v3.w, acc.w))));
                }
                for (; j < e; j++) {
                    int s = __ldg(g_ebuf + j);
                    float w = __ldg(ns + s);
                    float4 v = __ldg(xv + s * 32 + lane);
                    acc.x = fmaf(w, v.x, acc.x);
                    acc.y = fmaf(w, v.y, acc.y);
                    acc.z = fmaf(w, v.z, acc.z);
                    acc.w = fmaf(w, v.w, acc.w);
                }
                float sc = __ldg(nd + gr);
                acc.x *= sc; acc.y *= sc; acc.z *= sc; acc.w *= sc;
            }
            float* p = &As[row * APAD + lane * 4];
            p[0] = wmma::__float_to_tf32(acc.x);
            p[1] = wmma::__float_to_tf32(acc.y);
            p[2] = wmma::__float_to_tf32(acc.z);
            p[3] = wmma::__float_to_tf32(acc.w);
        }
        __syncthreads();

        #pragma unroll
        for (int ks = 0; ks < 16; ks++) {
            wmma::fragment<wmma::matrix_a, 16, 16, 8, wmma::precision::tf32, wmma::row_major> a;
            wmma::load_matrix_sync(a, &As[wrow * APAD + ks * 8], APAD);
            #pragma unroll
            for (int t = 0; t < 8; t++) {
                wmma::fragment<wmma::matrix_b, 16, 16, 8, wmma::precision::tf32, wmma::row_major> b;
                wmma::load_matrix_sync(b, &Bs[(kc * 128 + ks * 8) * BPAD + t * 16], BPAD);
                wmma::mma_sync(c[t], a, b, c[t]);
            }
        }
    }
    __syncthreads();

    // Epilogue: dump C to smem (reuse As), per-row relu(+bias) + L2 normalize.
    float* Cw = As + wrow * APAD;
    #pragma unroll
    for (int t = 0; t < 8; t++)
        wmma::store_matrix_sync(&Cw[t * 16], c[t], APAD, wmma::mem_row_major);
    __syncwarp();

    const int r = lane >> 1, half = lane & 1;
    const int gr = rowBase + wrow + r;
    const float* crow = &Cw[r * APAD + half * 64];
    const float* brow = &bs[half * 64];

    float ss = 0.f;
    #pragma unroll
    for (int j = 0; j < 64; j++) {
        float v = fmaxf(crow[j] + brow[j], 0.f);
        ss += v * v;
    }
    ss += __shfl_xor_sync(0xffffffffu, ss, 1);
    float inv = 1.0f / fmaxf(sqrtf(ss), 1e-12f);

    if (gr < M) {
        float4* op = (float4*)(out + (size_t)gr * DIM + half * 64);
        #pragma unroll
        for (int q = 0; q < 16; q++) {
            float4 o;
            o.x = fmaxf(crow[q * 4 + 0] + brow[q * 4 + 0], 0.f) * inv;
            o.y = fmaxf(crow[q * 4 + 1] + brow[q * 4 + 1], 0.f) * inv;
            o.z = fmaxf(crow[q * 4 + 2] + brow[q * 4 + 2], 0.f) * inv;
            o.w = fmaxf(crow[q * 4 + 3] + brow[q * 4 + 3], 0.f) * inv;
            op[q] = o;
        }
    }
}

// ---------------- launch ----------------
extern "C" void kernel_launch(void* const* d_in, const int* in_sizes, int n_in,
                              void* d_out, int out_size) {
    const float* x_drug = (const float*)d_in[0];
    const float* x_gene = (const float*)d_in[1];
    const float* W_dd   = (const float*)d_in[2];
    const float* W_dg   = (const float*)d_in[3];
    const float* W_gd   = (const float*)d_in[4];
    const float* W_gg   = (const float*)d_in[5];
    const float* h_bias = (const float*)d_in[6];
    const int* src_dd = (const int*)d_in[7];   const int* dst_dd = (const int*)d_in[8];
    const int* src_dg = (const int*)d_in[9];   const int* dst_dg = (const int*)d_in[10];
    const int* src_gd = (const int*)d_in[11];  const int* dst_gd = (const int*)d_in[12];
    const int* src_gg = (const int*)d_in[13];  const int* dst_gg = (const int*)d_in[14];
    float* out = (float*)d_out;

    const int E     = in_sizes[7];
    const int nDrug = in_sizes[0] / DIM;
    const int nGene = in_sizes[1] / DIM;

    // deg/norm segment offsets (8 segments)
    const int o_dd_s = 0;
    const int o_dd_d = o_dd_s + nDrug;
    const int o_dg_s = o_dd_d + nDrug;
    const int o_dg_d = o_dg_s + nDrug;
    const int o_gd_s = o_dg_d + nGene;
    const int o_gd_d = o_gd_s + nGene;
    const int o_gg_s = o_gd_d + nDrug;
    const int o_gg_d = o_gg_s + nGene;
    const int nTot   = o_gg_d + nGene;          // 600000
    const int nScan  = 2 * nDrug + 2 * nGene;   // 300000

    int *degP, *baseP;
    float *normP;
    cudaGetSymbolAddress((void**)&degP,  g_deg);
    cudaGetSymbolAddress((void**)&baseP, g_base);
    cudaGetSymbolAddress((void**)&normP, g_norm);

    zero_deg<<<(600000 / 4 + 255) / 256, 256>>>();

    const long long totDeg = 4LL * E;
    deg_all<<<(int)((totDeg + 255) / 256), 256>>>(
        src_dd, dst_dd, o_dd_s, o_dd_d,
        src_dg, dst_dg, o_dg_s, o_dg_d,
        src_gd, dst_gd, o_gd_s, o_gd_d,
        src_gg, dst_gg, o_gg_s, o_gg_d, E);

    norm_kernel<<<(nTot + 255) / 256, 256>>>(nTot);

    const int nScanBlk = (nScan + SCAN_BLK - 1) / SCAN_BLK;
    scan1<<<nScanBlk, 256>>>(nScan, nDrug, nGene, o_dd_d, o_gd_d, o_dg_d, o_gg_d);
    scan2<<<1, 512>>>(nScanBlk);
    scan3<<<(nScan + 255) / 256, 256>>>(nScan);

    bin_all<<<(int)((totDeg + 255) / 256), 256>>>(
        src_dd, dst_dd,
        src_gd, dst_gd,
        src_dg, dst_dg,
        src_gg, dst_gg, E, nDrug, nGene);

    cudaFuncSetAttribute(gemm_gather, cudaFuncAttributeMaxDynamicSharedMemorySize, GEMM_SMEM);
    // drug GEMM: etype0 = dd (x_drug), etype1 = gd (x_gene)
    gemm_gather<<<(nDrug + 127) / 128, 256, GEMM_SMEM>>>(
        x_drug, x_gene,
        baseP, baseP + nDrug,
        degP + o_dd_d, degP + o_gd_d,
        normP + o_dd_s, normP + o_gd_s,
        normP + o_dd_d, normP + o_gd_d,
        W_dd, W_gd, h_bias, out, nDrug);
    // gene GEMM: etype0 = dg (x_drug), etype1 = gg (x_gene)
    gemm_gather<<<(nGene + 127) / 128, 256, GEMM_SMEM>>>(
        x_drug, x_gene,
        baseP + 2 * nDrug, baseP + 2 * nDrug + nGene,
        degP + o_dg_d, degP + o_gg_d,
        normP + o_dg_s, normP + o_gg_s,
        normP + o_dg_d, normP + o_gg_d,
        W_dg, W_gg, h_bias, out + (size_t)nDrug * DIM, nGene);
}

// round 5
// speedup vs baseline: 1.6491x; 1.6491x over previous
#include <cuda_runtime.h>
#include <cstdint>
#include <math.h>
#include <mma.h>

using namespace nvcuda;

#define DIM  128
#define AGGC 256

// ---------------- scratch (device globals; no allocation allowed) ----------------
__device__ int   g_deg [600000];
__device__ float g_norm[600000];
__device__ int   g_base  [300000];   // CSR row starts: [dd | gd | dg | gg] (by dst)
__device__ int   g_cursor[300000];
__device__ int   g_bsum  [512];
__device__ int   g_ebuf  [2400000];  // binned src indices
__device__ float g_agg_drug[100000ull * AGGC];
__device__ float g_agg_gene[ 50000ull * AGGC];

// ---------------- zero deg ----------------
__global__ void zero_deg() {
    int i = blockIdx.x * blockDim.x + threadIdx.x;
    if (i < 600000 / 4) ((int4*)g_deg)[i] = make_int4(0, 0, 0, 0);
}

// ---------------- degree counting (all 4 etypes) ----------------
__global__ void deg_all(const int* __restrict__ s0, const int* __restrict__ d0, int o0s, int o0d,
                        const int* __restrict__ s1, const int* __restrict__ d1, int o1s, int o1d,
                        const int* __restrict__ s2, const int* __restrict__ d2, int o2s, int o2d,
                        const int* __restrict__ s3, const int* __restrict__ d3, int o3s, int o3d,
                        int E) {
    int i = blockIdx.x * blockDim.x + threadIdx.x;
    const int *s, *d; int os, od, j;
    if (i < E)          { s = s0; d = d0; os = o0s; od = o0d; j = i; }
    else if (i < 2 * E) { s = s1; d = d1; os = o1s; od = o1d; j = i - E; }
    else if (i < 3 * E) { s = s2; d = d2; os = o2s; od = o2d; j = i - 2 * E; }
    else if (i < 4 * E) { s = s3; d = d3; os = o3s; od = o3d; j = i - 3 * E; }
    else return;
    atomicAdd(&g_deg[os + __ldg(s + j)], 1);
    atomicAdd(&g_deg[od + __ldg(d + j)], 1);
}

__global__ void norm_kernel(int n) {
    int i = blockIdx.x * blockDim.x + threadIdx.x;
    if (i < n) g_norm[i] = rsqrtf(fmaxf((float)g_deg[i], 1.0f));
}

// ---------------- 3-phase exclusive scan over concatenated dst degrees ----------------
#define SCAN_BLK 1024
__global__ void scan1(int total, int nDrug, int nGene,
                      int o_dd_d, int o_gd_d, int o_dg_d, int o_gg_d) {
    __shared__ int sh[256];
    const int tid = threadIdx.x;
    const int base = blockIdx.x * SCAN_BLK + tid * 4;
    const int c1 = nDrug, c2 = 2 * nDrug, c3 = 2 * nDrug + nGene;
    int v[4], ssum = 0;
    #pragma unroll
    for (int q = 0; q < 4; q++) {
        int i = base + q, d = 0;
        if (i < total) {
            int idx;
            if (i < c1)      idx = o_dd_d + i;
            else if (i < c2) idx = o_gd_d + i - c1;
            else if (i < c3) idx = o_dg_d + i - c2;
            else             idx = o_gg_d + i - c3;
            d = g_deg[idx];
        }
        v[q] = d; ssum += d;
    }
    sh[tid] = ssum; __syncthreads();
    for (int off = 1; off < 256; off <<= 1) {
        int t = (tid >= off) ? sh[tid - off] : 0;
        __syncthreads();
        sh[tid] += t;
        __syncthreads();
    }
    int run = sh[tid] - ssum;
    if (tid == 255) g_bsum[blockIdx.x] = sh[255];
    #pragma unroll
    for (int q = 0; q < 4; q++) {
        int i = base + q;
        if (i < total) g_base[i] = run;
        run += v[q];
    }
}

__global__ void scan2(int n) {
    __shared__ int sh[512];
    int tid = threadIdx.x;
    int v = (tid < n) ? g_bsum[tid] : 0;
    sh[tid] = v; __syncthreads();
    for (int off = 1; off < 512; off <<= 1) {
        int t = (tid >= off) ? sh[tid - off] : 0;
        __syncthreads();
        sh[tid] += t;
        __syncthreads();
    }
    if (tid < n) g_bsum[tid] = sh[tid] - v;
}

__global__ void scan3(int total) {
    int i = blockIdx.x * blockDim.x + threadIdx.x;
    if (i < total) {
        int v = g_base[i] + g_bsum[i / SCAN_BLK];
        g_base[i] = v;
        g_cursor[i] = v;
    }
}

// ---------------- binning: ebuf[pos] = src (CSR by dst); segment order dd, gd, dg, gg ----------------
__global__ void bin_all(const int* __restrict__ s0, const int* __restrict__ d0,
                        const int* __restrict__ s1, const int* __restrict__ d1,
                        const int* __restrict__ s2, const int* __restrict__ d2,
                        const int* __restrict__ s3, const int* __restrict__ d3,
                        int E, int nDrug, int nGene) {
    int i = blockIdx.x * blockDim.x + threadIdx.x;
    const int *s, *d; int off, j;
    if (i < E)          { s = s0; d = d0; off = 0;                 j = i; }
    else if (i < 2 * E) { s = s1; d = d1; off = nDrug;             j = i - E; }
    else if (i < 3 * E) { s = s2; d = d2; off = 2 * nDrug;         j = i - 2 * E; }
    else if (i < 4 * E) { s = s3; d = d3; off = 2 * nDrug + nGene; j = i - 3 * E; }
    else return;
    int dd = __ldg(d + j);
    int pos = atomicAdd(&g_cursor[off + dd], 1);
    g_ebuf[pos] = __ldg(s + j);
}

// ---------------- dense aggregation: one warp per (dst,etype) row ----------------
// agg[dst, colOff..+127] = norm_dst * sum_e norm_src[src_e] * x[src_e, :]
// No atomics, no pre-zero: each 128-col half written exactly once.
__global__ void __launch_bounds__(256)
agg_gather(const float* __restrict__ x_drug, const float* __restrict__ x_gene,
           float* __restrict__ aggD, float* __restrict__ aggG,
           int nDrug, int nGene,
           int o_dd_s, int o_dd_d, int o_dg_s, int o_dg_d,
           int o_gd_s, int o_gd_d, int o_gg_s, int o_gg_d) {
    const int gw   = (blockIdx.x * blockDim.x + threadIdx.x) >> 5;
    const int lane = threadIdx.x & 31;
    const int nRows = 2 * nDrug + 2 * nGene;
    if (gw >= nRows) return;

    const float4* xv; float* agg; int row, colOff, osrc, odst;
    if (gw < nDrug)                     { row = gw;                     xv = (const float4*)x_drug; agg = aggD; colOff = 0;   osrc = o_dd_s; odst = o_dd_d; }
    else if (gw < 2 * nDrug)            { row = gw - nDrug;             xv = (const float4*)x_gene; agg = aggD; colOff = 128; osrc = o_gd_s; odst = o_gd_d; }
    else if (gw < 2 * nDrug + nGene)    { row = gw - 2 * nDrug;         xv = (const float4*)x_drug; agg = aggG; colOff = 0;   osrc = o_dg_s; odst = o_dg_d; }
    else                                { row = gw - 2 * nDrug - nGene; xv = (const float4*)x_gene; agg = aggG; colOff = 128; osrc = o_gg_s; odst = o_gg_d; }

    int j = __ldg(g_base + gw);
    const int e = j + __ldg(g_deg + odst + row);
    const float* ns = g_norm + osrc;

    float4 acc = make_float4(0.f, 0.f, 0.f, 0.f);
    for (; j + 4 <= e; j += 4) {
        int s0 = __ldg(g_ebuf + j),     s1 = __ldg(g_ebuf + j + 1);
        int s2 = __ldg(g_ebuf + j + 2), s3 = __ldg(g_ebuf + j + 3);
        float w0 = __ldg(ns + s0), w1 = __ldg(ns + s1);
        float w2 = __ldg(ns + s2), w3 = __ldg(ns + s3);
        float4 v0 = __ldg(xv + s0 * 32 + lane);
        float4 v1 = __ldg(xv + s1 * 32 + lane);
        float4 v2 = __ldg(xv + s2 * 32 + lane);
        float4 v3 = __ldg(xv + s3 * 32 + lane);
        acc.x = fmaf(w0, v0.x, fmaf(w1, v1.x, fmaf(w2, v2.x, fmaf(w3, v3.x, acc.x))));
        acc.y = fmaf(w0, v0.y, fmaf(w1, v1.y, fmaf(w2, v2.y, fmaf(w3, v3.y, acc.y))));
        acc.z = fmaf(w0, v0.z, fmaf(w1, v1.z, fmaf(w2, v2.z, fmaf(w3, v3.z, acc.z))));
        acc.w = fmaf(w0, v0.w, fmaf(w1, v1.w, fmaf(w2, v2.w, fmaf(w3, v3.w, acc.w))));
    }
    for (; j < e; j++) {
        int s = __ldg(g_ebuf + j);
        float w = __ldg(ns + s);
        float4 v = __ldg(xv + s * 32 + lane);
        acc.x = fmaf(w, v.x, acc.x);
        acc.y = fmaf(w, v.y, acc.y);
        acc.z = fmaf(w, v.z, acc.z);
        acc.w = fmaf(w, v.w, acc.w);
    }
    float sc = __ldg(g_norm + odst + row);
    acc.x *= sc; acc.y *= sc; acc.z *= sc; acc.w *= sc;
    *(float4*)(agg + (size_t)row * AGGC + colOff + lane * 4) = acc;
}

// ---------------- WMMA tf32 GEMM + bias + relu + L2-normalize (agg pre-scaled) ----------------
#define APAD 132
#define BPAD 132
#define GEMM_SMEM ((256 * BPAD + 128 * APAD + 128) * 4)   // 203264 B

__global__ void __launch_bounds__(256, 1)
gemm_wmma(const float* __restrict__ agg,
          const float* __restrict__ W0, const float* __restrict__ W1,
          const float* __restrict__ bias,
          float* __restrict__ out, int M) {
    extern __shared__ float sm[];
    float* Bs = sm;
    float* As = sm + 256 * BPAD;
    float* bs = sm + 256 * BPAD + 128 * APAD;
    const int tid = threadIdx.x, wid = tid >> 5, lane = tid & 31;

    if (tid < 128) bs[tid] = __ldg(bias + tid);

    for (int i = tid; i < 256 * 128; i += 256) {
        int k = i >> 7, n = i & 127;
        float v = (k < 128) ? __ldg(W0 + k * 128 + n) : __ldg(W1 + (k - 128) * 128 + n);
        Bs[k * BPAD + n] = wmma::__float_to_tf32(v);
    }

    const int rowBase = blockIdx.x * 128;
    const int wrow = wid * 16;

    wmma::fragment<wmma::accumulator, 16, 16, 8, float> c[8];
    #pragma unroll
    for (int t = 0; t < 8; t++) wmma::fill_fragment(c[t], 0.0f);

    for (int kc = 0; kc < 2; kc++) {
        __syncthreads();
        for (int i = tid; i < 4096; i += 256) {
            int m = i >> 5, kq = i & 31;
            int gr = rowBase + m;
            float4 v = make_float4(0.f, 0.f, 0.f, 0.f);
            if (gr < M)
                v = __ldg((const float4*)(agg + (size_t)gr * AGGC) + kc * 32 + kq);
            float* p = &As[m * APAD + kq * 4];
            p[0] = wmma::__float_to_tf32(v.x);
            p[1] = wmma::__float_to_tf32(v.y);
            p[2] = wmma::__float_to_tf32(v.z);
            p[3] = wmma::__float_to_tf32(v.w);
        }
        __syncthreads();

        #pragma unroll
        for (int ks = 0; ks < 16; ks++) {
            wmma::fragment<wmma::matrix_a, 16, 16, 8, wmma::precision::tf32, wmma::row_major> a;
            wmma::load_matrix_sync(a, &As[wrow * APAD + ks * 8], APAD);
            #pragma unroll
            for (int t = 0; t < 8; t++) {
                wmma::fragment<wmma::matrix_b, 16, 16, 8, wmma::precision::tf32, wmma::row_major> b;
                wmma::load_matrix_sync(b, &Bs[(kc * 128 + ks * 8) * BPAD + t * 16], BPAD);
                wmma::mma_sync(c[t], a, b, c[t]);
            }
        }
    }
    __syncthreads();

    float* Cw = As + wrow * APAD;
    #pragma unroll
    for (int t = 0; t < 8; t++)
        wmma::store_matrix_sync(&Cw[t * 16], c[t], APAD, wmma::mem_row_major);
    __syncwarp();

    const int r = lane >> 1, half = lane & 1;
    const int gr = rowBase + wrow + r;
    const float* crow = &Cw[r * APAD + half * 64];
    const float* brow = &bs[half * 64];

    float ss = 0.f;
    #pragma unroll
    for (int j = 0; j < 64; j++) {
        float v = fmaxf(crow[j] + brow[j], 0.f);
        ss += v * v;
    }
    ss += __shfl_xor_sync(0xffffffffu, ss, 1);
    float inv = 1.0f / fmaxf(sqrtf(ss), 1e-12f);

    if (gr < M) {
        float4* op = (float4*)(out + (size_t)gr * DIM + half * 64);
        #pragma unroll
        for (int q = 0; q < 16; q++) {
            float4 o;
            o.x = fmaxf(crow[q * 4 + 0] + brow[q * 4 + 0], 0.f) * inv;
            o.y = fmaxf(crow[q * 4 + 1] + brow[q * 4 + 1], 0.f) * inv;
            o.z = fmaxf(crow[q * 4 + 2] + brow[q * 4 + 2], 0.f) * inv;
            o.w = fmaxf(crow[q * 4 + 3] + brow[q * 4 + 3], 0.f) * inv;
            op[q] = o;
        }
    }
}

// ---------------- launch ----------------
extern "C" void kernel_launch(void* const* d_in, const int* in_sizes, int n_in,
                              void* d_out, int out_size) {
    const float* x_drug = (const float*)d_in[0];
    const float* x_gene = (const float*)d_in[1];
    const float* W_dd   = (const float*)d_in[2];
    const float* W_dg   = (const float*)d_in[3];
    const float* W_gd   = (const float*)d_in[4];
    const float* W_gg   = (const float*)d_in[5];
    const float* h_bias = (const float*)d_in[6];
    const int* src_dd = (const int*)d_in[7];   const int* dst_dd = (const int*)d_in[8];
    const int* src_dg = (const int*)d_in[9];   const int* dst_dg = (const int*)d_in[10];
    const int* src_gd = (const int*)d_in[11];  const int* dst_gd = (const int*)d_in[12];
    const int* src_gg = (const int*)d_in[13];  const int* dst_gg = (const int*)d_in[14];
    float* out = (float*)d_out;

    const int E     = in_sizes[7];
    const int nDrug = in_sizes[0] / DIM;
    const int nGene = in_sizes[1] / DIM;

    const int o_dd_s = 0;
    const int o_dd_d = o_dd_s + nDrug;
    const int o_dg_s = o_dd_d + nDrug;
    const int o_dg_d = o_dg_s + nDrug;
    const int o_gd_s = o_dg_d + nGene;
    const int o_gd_d = o_gd_s + nGene;
    const int o_gg_s = o_gd_d + nDrug;
    const int o_gg_d = o_gg_s + nGene;
    const int nTot   = o_gg_d + nGene;          // 600000
    const int nScan  = 2 * nDrug + 2 * nGene;   // 300000

    float *aggD, *aggG;
    cudaGetSymbolAddress((void**)&aggD, g_agg_drug);
    cudaGetSymbolAddress((void**)&aggG, g_agg_gene);

    zero_deg<<<(600000 / 4 + 255) / 256, 256>>>();

    const long long totDeg = 4LL * E;
    deg_all<<<(int)((totDeg + 255) / 256), 256>>>(
        src_dd, dst_dd, o_dd_s, o_dd_d,
        src_dg, dst_dg, o_dg_s, o_dg_d,
        src_gd, dst_gd, o_gd_s, o_gd_d,
        src_gg, dst_gg, o_gg_s, o_gg_d, E);

    norm_kernel<<<(nTot + 255) / 256, 256>>>(nTot);

    const int nScanBlk = (nScan + SCAN_BLK - 1) / SCAN_BLK;
    scan1<<<nScanBlk, 256>>>(nScan, nDrug, nGene, o_dd_d, o_gd_d, o_dg_d, o_gg_d);
    scan2<<<1, 512>>>(nScanBlk);
    scan3<<<(nScan + 255) / 256, 256>>>(nScan);

    bin_all<<<(int)((totDeg + 255) / 256), 256>>>(
        src_dd, dst_dd,
        src_gd, dst_gd,
        src_dg, dst_dg,
        src_gg, dst_gg, E, nDrug, nGene);

    // dense aggregation: one warp per (dst,etype) row
    const long long aggWarps = (long long)nScan * 32;
    agg_gather<<<(int)((aggWarps + 255) / 256), 256>>>(
        x_drug, x_gene, aggD, aggG, nDrug, nGene,
        o_dd_s, o_dd_d, o_dg_s, o_dg_d, o_gd_s, o_gd_d, o_gg_s, o_gg_d);

    cudaFuncSetAttribute(gemm_wmma, cudaFuncAttributeMaxDynamicSharedMemorySize, GEMM_SMEM);
    gemm_wmma<<<(nDrug + 127) / 128, 256, GEMM_SMEM>>>(
        aggD, W_dd, W_gd, h_bias, out, nDrug);
    gemm_wmma<<<(nGene + 127) / 128, 256, GEMM_SMEM>>>(
        aggG, W_dg, W_gg, h_bias, out + (size_t)nDrug * DIM, nGene);
}